// round 17
// baseline (speedup 1.0000x reference)
#include <cuda_runtime.h>
#include <cuda_fp16.h>

// ADDLoss — fp16x2 hot loop with ALL per-element setup hoisted into the prep
// launch (no new launch: prep grid 30 -> 94 blocks).
//  prep blocks [0,30):  pack points -> fp16x2 SoA groups (8 pts/group, 512 pad)
//  prep blocks [30,94): per-element coeffs -> half2-packed uint4 x3 (both
//                       halves equal, so a loaded u32 IS the half2 operand);
//                       exact pad-correction corr; trans-norm term folded into
//                       g_sum (fixed-point int atomic).
//  main: prologue = 3 broadcast LDG.128; per pair (2 pts): 13 half2 fma-pipe
//        ops; sqrt via bit-trick (half bits (h&0x7FFF)<<13 as f32 = x*2^-112,
//        sqrt.approx -> sqrt(x)*2^-56, FFMA-imm *2^56 accumulate).
// 16 lanes/elem, 2 elems/warp, 2048x128, exactly 4 groups/lane (no tail).

#define BATCH      16384
#define NPTS       500
#define NOBJ       30
#define NGROUPS    64                    // 8 points/group; 512 padded points
#define WARPS_PB   4
#define THREADS_PB (WARPS_PB * 32)       // 128
#define ELEMS_PW   2                     // elements per warp (16 lanes each)
#define NBLOCKS    (BATCH / (WARPS_PB * ELEMS_PW))   // 2048
#define COEF_BLOCKS (BATCH / 256)        // 64
#define PREP_BLOCKS (NOBJ + COEF_BLOCKS) // 94

#define FP_SCALE     68719476736.0       // 2^36
#define INV_FP_SCALE (1.0 / 68719476736.0)

typedef unsigned long long u64;
typedef unsigned int u32;

__device__ uint4 g_hx[NOBJ * NGROUPS];
__device__ uint4 g_hy[NOBJ * NGROUPS];
__device__ uint4 g_hz[NOBJ * NGROUPS];
__device__ uint4 g_cA[BATCH];            // {HS00|HS00, HS11, HS22, HS01}
__device__ uint4 g_cB[BATCH];            // {HS02, HS12, HC0, HC1}
__device__ uint4 g_cC[BATCH];            // {HC2, HT2, corr_f32_bits, pad}
__device__ u64 g_sum;                    // zero-init; self-resets each launch
__device__ u32 g_count;

__device__ __forceinline__ __half2 u2h(u32 u) { __half2 h; memcpy(&h, &u, 4); return h; }
__device__ __forceinline__ u32 h2u(__half2 h) { u32 u; memcpy(&u, &h, 4); return u; }

__device__ __forceinline__ float sqrt_abs(float x) {
    float r; asm("sqrt.approx.f32 %0, %1;" : "=f"(r) : "f"(fabsf(x))); return r;
}
// u holds x*2^-112 as f32 bits -> returns sqrt(x)*2^-56
__device__ __forceinline__ float sqrt_scaled(u32 u) {
    float r; asm("sqrt.approx.f32 %0, %1;" : "=f"(r) : "f"(__uint_as_float(u)));
    return r;
}

// ---- prep: points pack (blocks 0..29) + coefficients (blocks 30..93) -------
__global__ __launch_bounds__(256)
void addloss_prep(const float* __restrict__ points,
                  const float* __restrict__ pred_r,
                  const float* __restrict__ pred_t,
                  const float* __restrict__ gt_r,
                  const float* __restrict__ gt_t)
{
    const int tid = threadIdx.x;

    if (blockIdx.x < NOBJ) {
        // ---- points pack: coalesced stage through smem ----
        __shared__ float sp[1536];       // 512 padded points x 3 comps
        const int o = blockIdx.x;
        const float* src = points + (size_t)o * (NPTS * 3);
        for (int i = tid; i < 1536; i += 256)
            sp[i] = (i < NPTS * 3) ? src[i] : 0.f;
        __syncthreads();

        if (tid < NGROUPS) {
            float x[8], y[8], z[8];
            #pragma unroll
            for (int i = 0; i < 8; i++) {
                const int n = tid * 8 + i;
                x[i] = sp[3*n]; y[i] = sp[3*n+1]; z[i] = sp[3*n+2];
            }
            const int idx = o * NGROUPS + tid;
            g_hx[idx] = make_uint4(h2u(__floats2half2_rn(x[0],x[1])), h2u(__floats2half2_rn(x[2],x[3])),
                                   h2u(__floats2half2_rn(x[4],x[5])), h2u(__floats2half2_rn(x[6],x[7])));
            g_hy[idx] = make_uint4(h2u(__floats2half2_rn(y[0],y[1])), h2u(__floats2half2_rn(y[2],y[3])),
                                   h2u(__floats2half2_rn(y[4],y[5])), h2u(__floats2half2_rn(y[6],y[7])));
            g_hz[idx] = make_uint4(h2u(__floats2half2_rn(z[0],z[1])), h2u(__floats2half2_rn(z[2],z[3])),
                                   h2u(__floats2half2_rn(z[4],z[5])), h2u(__floats2half2_rn(z[6],z[7])));
        }
        return;
    }

    // ---- coefficients for batch element b ----
    const int b = (blockIdx.x - NOBJ) * 256 + tid;

    const float4 qp = reinterpret_cast<const float4*>(pred_r)[b];
    const float4 qg = reinterpret_cast<const float4*>(gt_r)[b];
    const float pw = qp.x, px_ = qp.y, py_ = qp.z, pz_ = qp.w;
    const float gw = qg.x, gx_ = qg.y, gy_ = qg.z, gz_ = qg.w;

    const float m00 = -2.f*(py_*py_ + pz_*pz_ - gy_*gy_ - gz_*gz_);
    const float m01 =  2.f*(px_*py_ - pw*pz_ - gx_*gy_ + gw*gz_);
    const float m02 =  2.f*(px_*pz_ + pw*py_ - gx_*gz_ - gw*gy_);
    const float m10 =  2.f*(px_*py_ + pw*pz_ - gx_*gy_ - gw*gz_);
    const float m11 = -2.f*(px_*px_ + pz_*pz_ - gx_*gx_ - gz_*gz_);
    const float m12 =  2.f*(py_*pz_ - pw*px_ - gy_*gz_ + gw*gx_);
    const float m20 =  2.f*(px_*pz_ - pw*py_ - gx_*gz_ + gw*gy_);
    const float m21 =  2.f*(py_*pz_ + pw*px_ - gy_*gz_ - gw*gx_);
    const float m22 = -2.f*(px_*px_ + py_*py_ - gx_*gx_ - gy_*gy_);

    const float tx = pred_t[3*b+0] - gt_t[3*b+0];
    const float ty = pred_t[3*b+1] - gt_t[3*b+1];
    const float tz = pred_t[3*b+2] - gt_t[3*b+2];
    const float t2 = tx*tx + ty*ty + tz*tz;

    const float s00 = m00*m00 + m10*m10 + m20*m20;
    const float s11 = m01*m01 + m11*m11 + m21*m21;
    const float s22 = m02*m02 + m12*m12 + m22*m22;
    const float s01 = 2.f*(m00*m01 + m10*m11 + m20*m21);
    const float s02 = 2.f*(m00*m02 + m10*m12 + m20*m22);
    const float s12 = 2.f*(m01*m02 + m11*m12 + m21*m22);
    const float c0  = 2.f*(m00*tx + m10*ty + m20*tz);
    const float c1  = 2.f*(m01*tx + m11*ty + m21*tz);
    const float c2  = 2.f*(m02*tx + m12*ty + m22*tz);

    const u32 uT2 = h2u(__float2half2_rn(t2));
    // exact pad correction: same instruction/path as main's sqrt chain
    const float corr = sqrt_scaled((uT2 & 0x7FFFu) << 13) * 0x1p56f;

    g_cA[b] = make_uint4(h2u(__float2half2_rn(s00)), h2u(__float2half2_rn(s11)),
                         h2u(__float2half2_rn(s22)), h2u(__float2half2_rn(s01)));
    g_cB[b] = make_uint4(h2u(__float2half2_rn(s02)), h2u(__float2half2_rn(s12)),
                         h2u(__float2half2_rn(c0)),  h2u(__float2half2_rn(c1)));
    g_cC[b] = make_uint4(h2u(__float2half2_rn(c2)), uT2, __float_as_uint(corr), 0u);

    // trans-norm contribution: fixed-order block reduce -> int atomic
    __shared__ float sh[256];
    sh[tid] = sqrt_abs(t2);
    __syncthreads();
    #pragma unroll
    for (int st = 128; st > 0; st >>= 1) {
        if (tid < st) sh[tid] += sh[tid + st];
        __syncthreads();
    }
    if (tid == 0) {
        const u64 q = (u64)__double2ll_rn((double)sh[0] * FP_SCALE);
        atomicAdd(&g_sum, q);
    }
}

// ---- main ------------------------------------------------------------------
__global__ __launch_bounds__(THREADS_PB)
void addloss_kernel(const int* __restrict__ obj_ids, float* __restrict__ out)
{
    const int warp_in_blk = threadIdx.x >> 5;
    const int lane        = threadIdx.x & 31;
    const int l16         = lane & 15;
    const int half        = lane >> 4;
    const int b = (blockIdx.x * WARPS_PB + warp_in_blk) * ELEMS_PW + half;

    __shared__ float sh_val[WARPS_PB];

    // ---- minimal prologue: 3 broadcast LDG.128 + index math ----
    int oid = obj_ids[b];
    oid = min(max(oid, 0), NOBJ - 1);
    const int gbase = oid * NGROUPS + l16;

    const uint4 cA = g_cA[b];
    const uint4 cB = g_cB[b];
    const uint4 cC = g_cC[b];
    // each u32 is directly a half2 operand (both halves equal)
    const __half2 HS00 = u2h(cA.x), HS11 = u2h(cA.y), HS22 = u2h(cA.z), HS01 = u2h(cA.w);
    const __half2 HS02 = u2h(cB.x), HS12 = u2h(cB.y), HC0  = u2h(cB.z), HC1  = u2h(cB.w);
    const __half2 HC2  = u2h(cC.x), HT2  = u2h(cC.y);
    const float   corr = __uint_as_float(cC.z);

    float acc0 = 0.f, acc1 = 0.f;

    #define PAIR(PXb, PYb, PZb) do {                                           \
        const __half2 hx = u2h(PXb), hy = u2h(PYb), hz = u2h(PZb);             \
        const __half2 U  = __hfma2(HS02, hz, __hfma2(HS01, hy, __hmul2(HS00, hx))); \
        const __half2 V  = __hfma2(HS12, hz, __hmul2(HS11, hy));               \
        const __half2 W  = __hmul2(HS22, hz);                                  \
        const __half2 A2 = __hfma2(hz, W, __hfma2(hy, V, __hmul2(hx, U)));     \
        const __half2 LN = __hfma2(HC0, hx, __hfma2(HC1, hy, __hfma2(HC2, hz, HT2))); \
        const __half2 B2 = __hadd2(A2, LN);                                    \
        const u32 ua = h2u(A2), ub = h2u(B2);                                  \
        acc0 = fmaf(sqrt_scaled((ua & 0x7FFFu) << 13), 0x1p56f, acc0);         \
        acc1 = fmaf(sqrt_scaled((ua >> 3) & 0x0FFFE000u), 0x1p56f, acc1);      \
        acc0 = fmaf(sqrt_scaled((ub & 0x7FFFu) << 13), 0x1p56f, acc0);         \
        acc1 = fmaf(sqrt_scaled((ub >> 3) & 0x0FFFE000u), 0x1p56f, acc1);      \
    } while (0)

    #define GROUP(X, Y, Z) do {                                                \
        PAIR((X).x, (Y).x, (Z).x);                                             \
        PAIR((X).y, (Y).y, (Z).y);                                             \
        PAIR((X).z, (Y).z, (Z).z);                                             \
        PAIR((X).w, (Y).w, (Z).w);                                             \
    } while (0)

    // ---- uniform pipelined loop: exactly 4 groups per lane (64 = 16*4) ----
    uint4 X = g_hx[gbase], Y = g_hy[gbase], Z = g_hz[gbase];
    #pragma unroll
    for (int k = 0; k < 4; ++k) {
        uint4 nX, nY, nZ;
        if (k < 3) {
            const int q = gbase + 16 * (k + 1);
            nX = g_hx[q]; nY = g_hy[q]; nZ = g_hz[q];
        }
        GROUP(X, Y, Z);
        X = nX; Y = nY; Z = nZ;
    }
    #undef GROUP
    #undef PAIR

    // ---- 16-lane segment reduce (fixed order -> deterministic) ----
    float s = acc0 + acc1;
    s += __shfl_down_sync(0xffffffffu, s, 8, 16);
    s += __shfl_down_sync(0xffffffffu, s, 4, 16);
    s += __shfl_down_sync(0xffffffffu, s, 2, 16);
    s += __shfl_down_sync(0xffffffffu, s, 1, 16);

    // 12 pad points each contributed exactly corr; trans term folded in prep
    const float s_elem = (s - 12.f * corr) * (1.0f / NPTS);

    const float e1 = __shfl_sync(0xffffffffu, s_elem, 16);

    if (lane == 0)
        sh_val[warp_in_blk] = s_elem + e1;
    __syncthreads();

    if (threadIdx.x == 0) {
        float blk = 0.f;
        #pragma unroll
        for (int w = 0; w < WARPS_PB; w++) blk += sh_val[w];

        const u64 q = (u64)__double2ll_rn((double)blk * FP_SCALE);
        atomicAdd(&g_sum, q);
        __threadfence();
        const u32 ticket = atomicAdd(&g_count, 1u);
        if (ticket == NBLOCKS - 1) {
            const u64 total = atomicExch(&g_sum, 0ULL);  // read + reset for replay
            g_count = 0u;
            out[0] = (float)((double)total * INV_FP_SCALE * (1.0 / BATCH));
        }
    }
}

extern "C" void kernel_launch(void* const* d_in, const int* in_sizes, int n_in,
                              void* d_out, int out_size)
{
    const float* pred_r  = (const float*)d_in[0];
    const float* pred_t  = (const float*)d_in[1];
    const float* gt_r    = (const float*)d_in[2];
    const float* gt_t    = (const float*)d_in[3];
    const int*   obj_ids = (const int*)  d_in[4];
    const float* points  = (const float*)d_in[5];
    float* out = (float*)d_out;

    addloss_prep<<<PREP_BLOCKS, 256>>>(points, pred_r, pred_t, gt_r, gt_t);
    addloss_kernel<<<NBLOCKS, THREADS_PB>>>(obj_ids, out);
}